// round 3
// baseline (speedup 1.0000x reference)
#include <cuda_runtime.h>
#include <cuda_bf16.h>

#define N_NODES   50000
#define N_EDGES   600000
#define HID       128
#define N_GRAPHS  128
#define N_CLASSES 10

// ---------------- scratch (no allocation allowed) ----------------
__device__ float g_h  [(size_t)N_NODES * HID];   // 25.6 MB  GEMM output / messages
__device__ float g_agg[(size_t)N_NODES * HID];   // 25.6 MB  aggregation buffer
__device__ float g_dinv[N_NODES];
__device__ int   g_deg [N_NODES];
__device__ float g_pool[N_GRAPHS * HID];
__device__ float g_cnt [N_GRAPHS];

// ---------------- small helper kernels ----------------
__global__ void zero_kernel() {
    int i = blockIdx.x * blockDim.x + threadIdx.x;
    if (i < N_NODES)        g_deg[i] = 0;
    if (i < N_GRAPHS * HID) g_pool[i] = 0.f;
    if (i < N_GRAPHS)       g_cnt[i] = 0.f;
}

__global__ void deg_kernel(const int* __restrict__ ei) {
    int e = blockIdx.x * blockDim.x + threadIdx.x;
    if (e < N_EDGES) atomicAdd(&g_deg[ei[N_EDGES + e]], 1);
}

__global__ void dinv_kernel() {
    int i = blockIdx.x * blockDim.x + threadIdx.x;
    if (i < N_NODES) g_dinv[i] = rsqrtf((float)g_deg[i] + 1.0f);
}

// agg[i,:] = h[i,:] * dinv[i]^2   (self-loop term; also initializes agg)
__global__ void init_agg_kernel() {
    int i = blockIdx.x * blockDim.x + threadIdx.x;   // float4 index
    if (i >= N_NODES * (HID / 4)) return;
    int node = i >> 5;                               // 32 float4 per row
    float d = g_dinv[node];
    float s = d * d;
    float4 v = ((const float4*)g_h)[i];
    v.x *= s; v.y *= s; v.z *= s; v.w *= s;
    ((float4*)g_agg)[i] = v;
}

// one warp per edge: gather h[row]*norm, atomic-add into agg[col]
__global__ void scatter_kernel(const int* __restrict__ ei) {
    int gt = blockIdx.x * blockDim.x + threadIdx.x;
    int e    = gt >> 5;
    int lane = gt & 31;
    if (e >= N_EDGES) return;
    int r = ei[e];
    int c = ei[N_EDGES + e];
    float norm = g_dinv[r] * g_dinv[c];
    float4 v = ((const float4*)(g_h + (size_t)r * HID))[lane];
    float* out = g_agg + (size_t)c * HID + lane * 4;
    atomicAdd(out + 0, v.x * norm);
    atomicAdd(out + 1, v.y * norm);
    atomicAdd(out + 2, v.z * norm);
    atomicAdd(out + 3, v.w * norm);
}

// ---------------- GEMM: g_h[n,128] = act(A) @ W[128,128] ----------------
// A == nullptr  -> input is g_agg
// preBias != 0  -> input transform  a = relu(a + preBias[k])
// postBias != 0 -> output transform c = relu(c + postBias[col])
// 64-row tile, two K-chunks of 64. Static smem = exactly 48 KB.
#define TM 64

__global__ __launch_bounds__(256) void gemm_kernel(
    const float* __restrict__ A, const float* __restrict__ W, int n,
    const float* __restrict__ preBias, const float* __restrict__ postBias)
{
    __shared__ float ws[64][128];   // 32 KB : k-chunk x col
    __shared__ float xs[64][64];    // 16 KB : row x k-chunk

    const float* Ain = A ? A : g_agg;

    int tid  = threadIdx.x;
    int row0 = blockIdx.x * TM;
    int g  = tid >> 4;              // row group 0..15 -> rows g+16i
    int tx = tid & 15;              // col group      -> cols tx+16j

    float acc[4][8];
    #pragma unroll
    for (int i = 0; i < 4; i++)
        #pragma unroll
        for (int j = 0; j < 8; j++) acc[i][j] = 0.f;

    for (int kc = 0; kc < 2; kc++) {
        // W chunk: 64 k-rows x 128 cols = 2048 float4 / 256 thr = 8 each
        const float4* W4 = (const float4*)(W + kc * 64 * 128);
        #pragma unroll
        for (int i = 0; i < 8; i++) {
            int j = tid + i * 256;
            ((float4*)ws)[j] = W4[j];
        }
        // X chunk: 64 rows x 16 float4 = 1024 float4 / 256 thr = 4 each
        #pragma unroll
        for (int i = 0; i < 4; i++) {
            int j  = tid + i * 256;
            int r  = j >> 4;
            int k4 = j & 15;
            int row = row0 + r;
            float4 v = make_float4(0.f, 0.f, 0.f, 0.f);
            if (row < n) v = ((const float4*)Ain)[row * 32 + kc * 16 + k4];
            if (preBias) {
                float4 b = ((const float4*)preBias)[kc * 16 + k4];
                v.x = fmaxf(v.x + b.x, 0.f);
                v.y = fmaxf(v.y + b.y, 0.f);
                v.z = fmaxf(v.z + b.z, 0.f);
                v.w = fmaxf(v.w + b.w, 0.f);
            }
            *(float4*)&xs[r][k4 * 4] = v;
        }
        __syncthreads();

        #pragma unroll 4
        for (int k = 0; k < 64; k++) {
            float a0 = xs[g     ][k];
            float a1 = xs[g + 16][k];
            float a2 = xs[g + 32][k];
            float a3 = xs[g + 48][k];
            #pragma unroll
            for (int j = 0; j < 8; j++) {
                float b = ws[k][tx + 16 * j];
                acc[0][j] = fmaf(a0, b, acc[0][j]);
                acc[1][j] = fmaf(a1, b, acc[1][j]);
                acc[2][j] = fmaf(a2, b, acc[2][j]);
                acc[3][j] = fmaf(a3, b, acc[3][j]);
            }
        }
        __syncthreads();
    }

    // epilogue -> g_h
    #pragma unroll
    for (int i = 0; i < 4; i++) {
        int row = row0 + g + 16 * i;
        if (row >= n) continue;
        #pragma unroll
        for (int j = 0; j < 8; j++) {
            float v = acc[i][j];
            int col = tx + 16 * j;
            if (postBias) v = fmaxf(v + postBias[col], 0.f);
            g_h[(size_t)row * HID + col] = v;
        }
    }
}

// ---------------- global mean pool (batch is sorted) ----------------
#define POOL_CH 512
__global__ void pool_kernel(const int* __restrict__ batch) {
    int t = threadIdx.x;                        // 128: feature column
    int start = blockIdx.x * POOL_CH;
    if (start >= N_NODES) return;
    int end = min(start + POOL_CH, N_NODES);
    int cur = batch[start];
    float acc = 0.f, cnt = 0.f;
    for (int i = start; i < end; i++) {
        int b = batch[i];
        if (b != cur) {
            atomicAdd(&g_pool[cur * HID + t], acc);
            if (t == 0) atomicAdd(&g_cnt[cur], cnt);
            acc = 0.f; cnt = 0.f; cur = b;
        }
        acc += g_h[(size_t)i * HID + t];
        cnt += 1.f;
    }
    atomicAdd(&g_pool[cur * HID + t], acc);
    if (t == 0) atomicAdd(&g_cnt[cur], cnt);
}

// ---------------- final head: mean, embeddings out, logits ----------------
__global__ void final_kernel(const float* __restrict__ Wlin,
                             const float* __restrict__ blin,
                             float* __restrict__ out) {
    int g = blockIdx.x;         // graph
    int t = threadIdx.x;        // 128
    __shared__ float p[HID];
    float c = fmaxf(g_cnt[g], 1.0f);
    float v = g_pool[g * HID + t] / c;
    out[N_GRAPHS * N_CLASSES + g * HID + t] = v;   // embeddings after logits
    p[t] = v;
    __syncthreads();
    if (t < N_CLASSES) {
        float s = blin[t];
        #pragma unroll 8
        for (int j = 0; j < HID; j++) s += p[j] * Wlin[j * N_CLASSES + t];
        out[g * N_CLASSES + t] = s;
    }
}

// ---------------- launch ----------------
extern "C" void kernel_launch(void* const* d_in, const int* in_sizes, int n_in,
                              void* d_out, int out_size)
{
    const float* x     = (const float*)d_in[0];
    const int*   ei    = (const int*)d_in[1];      // int32! (JAX x64 disabled)
    const int*   batch = (const int*)d_in[2];
    const float* W[6] = {(const float*)d_in[3],  (const float*)d_in[5],
                         (const float*)d_in[7],  (const float*)d_in[9],
                         (const float*)d_in[11], (const float*)d_in[13]};
    const float* b[6] = {(const float*)d_in[4],  (const float*)d_in[6],
                         (const float*)d_in[8],  (const float*)d_in[10],
                         (const float*)d_in[12], (const float*)d_in[14]};
    const float* Wlin = (const float*)d_in[15];
    const float* blin = (const float*)d_in[16];
    float* out = (float*)d_out;

    zero_kernel<<<(N_NODES + 255) / 256, 256>>>();
    deg_kernel <<<(N_EDGES + 255) / 256, 256>>>(ei);
    dinv_kernel<<<(N_NODES + 255) / 256, 256>>>();

    const int gemm_grid    = (N_NODES + TM - 1) / TM;               // 782
    const int init_grid    = (N_NODES * (HID / 4) + 255) / 256;     // 6250
    const int scatter_grid = (N_EDGES * 32 + 255) / 256;            // 75000

    for (int l = 0; l < 5; l++) {
        const float* in  = (l == 0) ? x : nullptr;       // null -> g_agg
        const float* pre = (l == 0) ? nullptr : b[l - 1];
        gemm_kernel<<<gemm_grid, 256>>>(in, W[l], N_NODES, pre, nullptr);
        init_agg_kernel<<<init_grid, 256>>>();
        scatter_kernel <<<scatter_grid, 256>>>(ei);
    }
    // FC layer: relu(agg5 + b5) @ Wfc, fused relu(+bfc) on store
    gemm_kernel<<<gemm_grid, 256>>>(nullptr, W[5], N_NODES, b[4], b[5]);

    pool_kernel <<<(N_NODES + POOL_CH - 1) / POOL_CH, 128>>>(batch);
    final_kernel<<<N_GRAPHS, 128>>>(Wlin, blin, out);
}

// round 4
// speedup vs baseline: 1.7989x; 1.7989x over previous
#include <cuda_runtime.h>
#include <cuda_bf16.h>

#define N_NODES   50000
#define N_EDGES   600000
#define HID       128
#define N_GRAPHS  128
#define N_CLASSES 10

// ---------------- scratch (no allocation allowed) ----------------
__device__ float g_h  [(size_t)N_NODES * HID];   // 25.6 MB  GEMM output / messages
__device__ float g_agg[(size_t)N_NODES * HID];   // 25.6 MB  aggregation buffer
__device__ float g_dinv[N_NODES];
__device__ int   g_deg [N_NODES];
__device__ int2  g_edge[N_EDGES];                // packed (src,dst)
__device__ float g_norm[N_EDGES];                // dinv[src]*dinv[dst]
__device__ float g_pool[N_GRAPHS * HID];
__device__ float g_cnt [N_GRAPHS];

// ---------------- small helper kernels ----------------
__global__ void zero_kernel() {
    int i = blockIdx.x * blockDim.x + threadIdx.x;
    if (i < N_NODES)        g_deg[i] = 0;
    if (i < N_GRAPHS * HID) g_pool[i] = 0.f;
    if (i < N_GRAPHS)       g_cnt[i] = 0.f;
}

__global__ void deg_kernel(const int* __restrict__ ei) {
    int e = blockIdx.x * blockDim.x + threadIdx.x;
    if (e < N_EDGES) atomicAdd(&g_deg[ei[N_EDGES + e]], 1);
}

__global__ void dinv_kernel() {
    int i = blockIdx.x * blockDim.x + threadIdx.x;
    if (i < N_NODES) g_dinv[i] = rsqrtf((float)g_deg[i] + 1.0f);
}

// pack edges + precompute norms (reused by all 5 layers)
__global__ void prep_kernel(const int* __restrict__ ei) {
    int e = blockIdx.x * blockDim.x + threadIdx.x;
    if (e >= N_EDGES) return;
    int r = ei[e];
    int c = ei[N_EDGES + e];
    g_edge[e] = make_int2(r, c);
    g_norm[e] = g_dinv[r] * g_dinv[c];
}

// one warp per edge: gather h[src]*norm, vector-reduce into agg[dst]
__global__ void scatter_kernel() {
    int gt = blockIdx.x * blockDim.x + threadIdx.x;
    int e    = gt >> 5;
    int lane = gt & 31;
    if (e >= N_EDGES) return;
    int2  rc   = g_edge[e];
    float norm = g_norm[e];
    float4 v = ((const float4*)(g_h + (size_t)rc.x * HID))[lane];
    float* out = g_agg + (size_t)rc.y * HID + lane * 4;
    asm volatile("red.global.add.v4.f32 [%0], {%1, %2, %3, %4};"
                 :: "l"(out), "f"(v.x * norm), "f"(v.y * norm),
                    "f"(v.z * norm), "f"(v.w * norm)
                 : "memory");
}

// ---------------- GEMM: g_h[n,128] = act(A) @ W[128,128] ----------------
// A == nullptr  -> input is g_agg
// preBias != 0  -> input transform  a = relu(a + preBias[k])
// postBias != 0 -> output transform c = relu(c + postBias[col])
// selfInit      -> also write g_agg[row] = c * dinv[row]^2  (self-loop init)
// 64-row tile, two K-chunks of 64. Static smem = 48 KB.
// Per thread: 8 rows (wid+8i, warp-uniform smem reads) x 8 cols
// (lane*2, lane*2+1, lane*2+64, lane*2+65 -> two f32x2 pairs, conflict-free).
#define TM 64

__global__ __launch_bounds__(256) void gemm_kernel(
    const float* __restrict__ A, const float* __restrict__ W, int n,
    const float* __restrict__ preBias, const float* __restrict__ postBias,
    int selfInit)
{
    __shared__ float ws[64][128];   // 32 KB : k-chunk x col
    __shared__ float xs[64][64];    // 16 KB : row x k-chunk

    const float* Ain = A ? A : g_agg;

    int tid  = threadIdx.x;
    int row0 = blockIdx.x * TM;
    int wid  = tid >> 5;            // 0..7 : rows wid + 8i
    int lane = tid & 31;            // cols lane*2 (+64)

    unsigned long long acc[8][2];
    #pragma unroll
    for (int i = 0; i < 8; i++) { acc[i][0] = 0ull; acc[i][1] = 0ull; }

    #pragma unroll
    for (int kc = 0; kc < 2; kc++) {
        // W chunk: 64 k-rows x 128 cols = 2048 float4 / 256 thr = 8 each
        const float4* W4 = (const float4*)(W + kc * 64 * 128);
        #pragma unroll
        for (int i = 0; i < 8; i++) {
            int j = tid + i * 256;
            ((float4*)ws)[j] = W4[j];
        }
        // X chunk: 64 rows x 16 float4 = 1024 float4 / 256 thr = 4 each
        #pragma unroll
        for (int i = 0; i < 4; i++) {
            int j  = tid + i * 256;
            int r  = j >> 4;
            int k4 = j & 15;
            int row = row0 + r;
            float4 v = make_float4(0.f, 0.f, 0.f, 0.f);
            if (row < n) v = ((const float4*)Ain)[row * 32 + kc * 16 + k4];
            if (preBias) {
                float4 b = ((const float4*)preBias)[kc * 16 + k4];
                v.x = fmaxf(v.x + b.x, 0.f);
                v.y = fmaxf(v.y + b.y, 0.f);
                v.z = fmaxf(v.z + b.z, 0.f);
                v.w = fmaxf(v.w + b.w, 0.f);
            }
            *(float4*)&xs[r][k4 * 4] = v;
        }
        __syncthreads();

        #pragma unroll 4
        for (int k = 0; k < 64; k++) {
            // b pairs: conflict-free 64-bit loads (lanes 8B apart)
            unsigned long long b0 = *(const unsigned long long*)&ws[k][lane * 2];
            unsigned long long b1 = *(const unsigned long long*)&ws[k][lane * 2 + 64];
            #pragma unroll
            for (int i = 0; i < 8; i++) {
                float a = xs[wid + 8 * i][k];      // warp-uniform broadcast
                unsigned long long ap;
                asm("mov.b64 %0, {%1, %1};" : "=l"(ap) : "f"(a));
                asm("fma.rn.f32x2 %0, %1, %2, %0;" : "+l"(acc[i][0]) : "l"(ap), "l"(b0));
                asm("fma.rn.f32x2 %0, %1, %2, %0;" : "+l"(acc[i][1]) : "l"(ap), "l"(b1));
            }
        }
        __syncthreads();
    }

    // epilogue -> g_h (and optionally g_agg self-loop init)
    int c0 = lane * 2;
    int c1 = lane * 2 + 64;
    #pragma unroll
    for (int i = 0; i < 8; i++) {
        int row = row0 + wid + 8 * i;
        if (row >= n) continue;
        float lo0, hi0, lo1, hi1;
        asm("mov.b64 {%0, %1}, %2;" : "=f"(lo0), "=f"(hi0) : "l"(acc[i][0]));
        asm("mov.b64 {%0, %1}, %2;" : "=f"(lo1), "=f"(hi1) : "l"(acc[i][1]));
        if (postBias) {
            lo0 = fmaxf(lo0 + postBias[c0],     0.f);
            hi0 = fmaxf(hi0 + postBias[c0 + 1], 0.f);
            lo1 = fmaxf(lo1 + postBias[c1],     0.f);
            hi1 = fmaxf(hi1 + postBias[c1 + 1], 0.f);
        }
        float2 o0; o0.x = lo0; o0.y = hi0;
        float2 o1; o1.x = lo1; o1.y = hi1;
        *(float2*)&g_h[(size_t)row * HID + c0] = o0;
        *(float2*)&g_h[(size_t)row * HID + c1] = o1;
        if (selfInit) {
            float d = g_dinv[row];
            float s = d * d;
            float2 a0; a0.x = lo0 * s; a0.y = hi0 * s;
            float2 a1; a1.x = lo1 * s; a1.y = hi1 * s;
            *(float2*)&g_agg[(size_t)row * HID + c0] = a0;
            *(float2*)&g_agg[(size_t)row * HID + c1] = a1;
        }
    }
}

// ---------------- global mean pool (batch is sorted) ----------------
#define POOL_CH 512
__global__ void pool_kernel(const int* __restrict__ batch) {
    int t = threadIdx.x;                        // 128: feature column
    int start = blockIdx.x * POOL_CH;
    if (start >= N_NODES) return;
    int end = min(start + POOL_CH, N_NODES);
    int cur = batch[start];
    float acc = 0.f, cnt = 0.f;
    for (int i = start; i < end; i++) {
        int b = batch[i];
        if (b != cur) {
            atomicAdd(&g_pool[cur * HID + t], acc);
            if (t == 0) atomicAdd(&g_cnt[cur], cnt);
            acc = 0.f; cnt = 0.f; cur = b;
        }
        acc += g_h[(size_t)i * HID + t];
        cnt += 1.f;
    }
    atomicAdd(&g_pool[cur * HID + t], acc);
    if (t == 0) atomicAdd(&g_cnt[cur], cnt);
}

// ---------------- final head: mean, embeddings out, logits ----------------
__global__ void final_kernel(const float* __restrict__ Wlin,
                             const float* __restrict__ blin,
                             float* __restrict__ out) {
    int g = blockIdx.x;         // graph
    int t = threadIdx.x;        // 128
    __shared__ float p[HID];
    float c = fmaxf(g_cnt[g], 1.0f);
    float v = g_pool[g * HID + t] / c;
    out[N_GRAPHS * N_CLASSES + g * HID + t] = v;   // embeddings after logits
    p[t] = v;
    __syncthreads();
    if (t < N_CLASSES) {
        float s = blin[t];
        #pragma unroll 8
        for (int j = 0; j < HID; j++) s += p[j] * Wlin[j * N_CLASSES + t];
        out[g * N_CLASSES + t] = s;
    }
}

// ---------------- launch ----------------
extern "C" void kernel_launch(void* const* d_in, const int* in_sizes, int n_in,
                              void* d_out, int out_size)
{
    const float* x     = (const float*)d_in[0];
    const int*   ei    = (const int*)d_in[1];      // int32 (JAX x64 disabled)
    const int*   batch = (const int*)d_in[2];
    const float* W[6] = {(const float*)d_in[3],  (const float*)d_in[5],
                         (const float*)d_in[7],  (const float*)d_in[9],
                         (const float*)d_in[11], (const float*)d_in[13]};
    const float* b[6] = {(const float*)d_in[4],  (const float*)d_in[6],
                         (const float*)d_in[8],  (const float*)d_in[10],
                         (const float*)d_in[12], (const float*)d_in[14]};
    const float* Wlin = (const float*)d_in[15];
    const float* blin = (const float*)d_in[16];
    float* out = (float*)d_out;

    zero_kernel<<<(N_NODES + 255) / 256, 256>>>();
    deg_kernel <<<(N_EDGES + 255) / 256, 256>>>(ei);
    dinv_kernel<<<(N_NODES + 255) / 256, 256>>>();
    prep_kernel<<<(N_EDGES + 255) / 256, 256>>>(ei);

    const int gemm_grid    = (N_NODES + TM - 1) / TM;               // 782
    const int scatter_grid = (N_EDGES * 32 + 255) / 256;            // 75000

    for (int l = 0; l < 5; l++) {
        const float* in  = (l == 0) ? x : nullptr;       // null -> g_agg
        const float* pre = (l == 0) ? nullptr : b[l - 1];
        gemm_kernel<<<gemm_grid, 256>>>(in, W[l], N_NODES, pre, nullptr, 1);
        scatter_kernel<<<scatter_grid, 256>>>();
    }
    // FC layer: relu(agg5 + b5) @ Wfc, fused relu(+bfc) on store
    gemm_kernel<<<gemm_grid, 256>>>(nullptr, W[5], N_NODES, b[4], b[5], 0);

    pool_kernel <<<(N_NODES + POOL_CH - 1) / POOL_CH, 128>>>(batch);
    final_kernel<<<N_GRAPHS, 128>>>(Wlin, blin, out);
}

// round 5
// speedup vs baseline: 2.1673x; 1.2048x over previous
#include <cuda_runtime.h>
#include <cuda_bf16.h>

#define N_NODES   50000
#define N_EDGES   600000
#define HID       128
#define N_GRAPHS  128
#define N_CLASSES 10

// ---------------- scratch (no allocation allowed) ----------------
__device__ float g_h  [(size_t)N_NODES * HID];   // 25.6 MB  GEMM output (dinv-scaled for conv layers)
__device__ float g_agg[(size_t)N_NODES * HID];   // 25.6 MB  aggregation buffer
__device__ float g_dinv[N_NODES];
__device__ int   g_deg [N_NODES];                // in-degree (excl. self loop)
__device__ int   g_cur [N_NODES];                // placement cursor
__device__ int   g_rowptr[N_NODES + 1];          // CSR row pointers (by dst)
__device__ int   g_csr_src[N_EDGES];             // CSR source indices
__device__ float g_pool[N_GRAPHS * HID];
__device__ float g_cnt [N_GRAPHS];

// ---------------- setup kernels ----------------
__global__ void zero_kernel() {
    int i = blockIdx.x * blockDim.x + threadIdx.x;
    if (i < N_NODES)      { g_deg[i] = 0; g_cur[i] = 0; }
    if (i < N_GRAPHS * HID) g_pool[i] = 0.f;
    if (i < N_GRAPHS)       g_cnt[i] = 0.f;
}

__global__ void deg_kernel(const int* __restrict__ ei) {
    int e = blockIdx.x * blockDim.x + threadIdx.x;
    if (e < N_EDGES) atomicAdd(&g_deg[ei[N_EDGES + e]], 1);
}

__global__ void dinv_kernel() {
    int i = blockIdx.x * blockDim.x + threadIdx.x;
    if (i < N_NODES) g_dinv[i] = rsqrtf((float)g_deg[i] + 1.0f);
}

// single-block inclusive scan of g_deg -> g_rowptr (exclusive form)
__global__ void scan_kernel() {
    __shared__ int sdata[1024];
    __shared__ int carry;
    if (threadIdx.x == 0) carry = 0;
    __syncthreads();
    for (int base = 0; base < N_NODES; base += 1024) {
        int i = base + (int)threadIdx.x;
        int v = (i < N_NODES) ? g_deg[i] : 0;
        sdata[threadIdx.x] = v;
        __syncthreads();
        #pragma unroll
        for (int off = 1; off < 1024; off <<= 1) {
            int t = (threadIdx.x >= off) ? sdata[threadIdx.x - off] : 0;
            __syncthreads();
            sdata[threadIdx.x] += t;
            __syncthreads();
        }
        if (i < N_NODES) g_rowptr[i + 1] = carry + sdata[threadIdx.x];
        __syncthreads();
        if (threadIdx.x == 1023) carry += sdata[1023];
        __syncthreads();
    }
    if (threadIdx.x == 0) g_rowptr[0] = 0;
}

__global__ void place_kernel(const int* __restrict__ ei) {
    int e = blockIdx.x * blockDim.x + threadIdx.x;
    if (e >= N_EDGES) return;
    int r = ei[e];
    int c = ei[N_EDGES + e];
    int pos = g_rowptr[c] + atomicAdd(&g_cur[c], 1);
    g_csr_src[pos] = r;
}

// ---------------- aggregation: pure gather, no atomics ----------------
// g_h holds h_scaled = h*dinv (written by GEMM epilogue).
// agg[i] = dinv[i] * ( h_scaled[i] + sum_{src in N(i)} h_scaled[src] )
__global__ __launch_bounds__(256) void gather_kernel() {
    int gt   = blockIdx.x * blockDim.x + threadIdx.x;
    int node = gt >> 5;
    int lane = gt & 31;
    if (node >= N_NODES) return;

    const float4* h4 = (const float4*)g_h;
    float4 acc = h4[(size_t)node * 32 + lane];     // self-loop term
    int j  = g_rowptr[node];
    int e1 = g_rowptr[node + 1];

    for (; j + 4 <= e1; j += 4) {
        int s0 = g_csr_src[j];
        int s1 = g_csr_src[j + 1];
        int s2 = g_csr_src[j + 2];
        int s3 = g_csr_src[j + 3];
        float4 v0 = h4[(size_t)s0 * 32 + lane];
        float4 v1 = h4[(size_t)s1 * 32 + lane];
        float4 v2 = h4[(size_t)s2 * 32 + lane];
        float4 v3 = h4[(size_t)s3 * 32 + lane];
        acc.x += (v0.x + v1.x) + (v2.x + v3.x);
        acc.y += (v0.y + v1.y) + (v2.y + v3.y);
        acc.z += (v0.z + v1.z) + (v2.z + v3.z);
        acc.w += (v0.w + v1.w) + (v2.w + v3.w);
    }
    for (; j < e1; j++) {
        int s = g_csr_src[j];
        float4 v = h4[(size_t)s * 32 + lane];
        acc.x += v.x; acc.y += v.y; acc.z += v.z; acc.w += v.w;
    }
    float d = g_dinv[node];
    acc.x *= d; acc.y *= d; acc.z *= d; acc.w *= d;
    ((float4*)g_agg)[(size_t)node * 32 + lane] = acc;
}

// ---------------- GEMM: g_h[n,128] = act(A) @ W[128,128] ----------------
// A == nullptr  -> input is g_agg
// preBias != 0  -> input transform  a = relu(a + preBias[k])
// postBias != 0 -> output transform c = relu(c + postBias[col])
// scaleOut      -> store c * dinv[row]  (conv layers; feeds gather)
#define TM 64

__global__ __launch_bounds__(256) void gemm_kernel(
    const float* __restrict__ A, const float* __restrict__ W, int n,
    const float* __restrict__ preBias, const float* __restrict__ postBias,
    int scaleOut)
{
    __shared__ float ws[64][128];   // 32 KB : k-chunk x col
    __shared__ float xs[64][64];    // 16 KB : row x k-chunk

    const float* Ain = A ? A : g_agg;

    int tid  = threadIdx.x;
    int row0 = blockIdx.x * TM;
    int wid  = tid >> 5;            // 0..7 : rows wid + 8i
    int lane = tid & 31;            // cols lane*2 (+64)

    unsigned long long acc[8][2];
    #pragma unroll
    for (int i = 0; i < 8; i++) { acc[i][0] = 0ull; acc[i][1] = 0ull; }

    #pragma unroll
    for (int kc = 0; kc < 2; kc++) {
        const float4* W4 = (const float4*)(W + kc * 64 * 128);
        #pragma unroll
        for (int i = 0; i < 8; i++) {
            int j = tid + i * 256;
            ((float4*)ws)[j] = W4[j];
        }
        #pragma unroll
        for (int i = 0; i < 4; i++) {
            int j  = tid + i * 256;
            int r  = j >> 4;
            int k4 = j & 15;
            int row = row0 + r;
            float4 v = make_float4(0.f, 0.f, 0.f, 0.f);
            if (row < n) v = ((const float4*)Ain)[row * 32 + kc * 16 + k4];
            if (preBias) {
                float4 b = ((const float4*)preBias)[kc * 16 + k4];
                v.x = fmaxf(v.x + b.x, 0.f);
                v.y = fmaxf(v.y + b.y, 0.f);
                v.z = fmaxf(v.z + b.z, 0.f);
                v.w = fmaxf(v.w + b.w, 0.f);
            }
            *(float4*)&xs[r][k4 * 4] = v;
        }
        __syncthreads();

        #pragma unroll 4
        for (int k = 0; k < 64; k++) {
            unsigned long long b0 = *(const unsigned long long*)&ws[k][lane * 2];
            unsigned long long b1 = *(const unsigned long long*)&ws[k][lane * 2 + 64];
            #pragma unroll
            for (int i = 0; i < 8; i++) {
                float a = xs[wid + 8 * i][k];      // warp-uniform broadcast
                unsigned long long ap;
                asm("mov.b64 %0, {%1, %1};" : "=l"(ap) : "f"(a));
                asm("fma.rn.f32x2 %0, %1, %2, %0;" : "+l"(acc[i][0]) : "l"(ap), "l"(b0));
                asm("fma.rn.f32x2 %0, %1, %2, %0;" : "+l"(acc[i][1]) : "l"(ap), "l"(b1));
            }
        }
        __syncthreads();
    }

    int c0 = lane * 2;
    int c1 = lane * 2 + 64;
    #pragma unroll
    for (int i = 0; i < 8; i++) {
        int row = row0 + wid + 8 * i;
        if (row >= n) continue;
        float lo0, hi0, lo1, hi1;
        asm("mov.b64 {%0, %1}, %2;" : "=f"(lo0), "=f"(hi0) : "l"(acc[i][0]));
        asm("mov.b64 {%0, %1}, %2;" : "=f"(lo1), "=f"(hi1) : "l"(acc[i][1]));
        if (postBias) {
            lo0 = fmaxf(lo0 + postBias[c0],     0.f);
            hi0 = fmaxf(hi0 + postBias[c0 + 1], 0.f);
            lo1 = fmaxf(lo1 + postBias[c1],     0.f);
            hi1 = fmaxf(hi1 + postBias[c1 + 1], 0.f);
        }
        if (scaleOut) {
            float d = g_dinv[row];
            lo0 *= d; hi0 *= d; lo1 *= d; hi1 *= d;
        }
        float2 o0; o0.x = lo0; o0.y = hi0;
        float2 o1; o1.x = lo1; o1.y = hi1;
        *(float2*)&g_h[(size_t)row * HID + c0] = o0;
        *(float2*)&g_h[(size_t)row * HID + c1] = o1;
    }
}

// ---------------- global mean pool (batch is sorted) ----------------
#define POOL_CH 512
__global__ void pool_kernel(const int* __restrict__ batch) {
    int t = threadIdx.x;                        // 128: feature column
    int start = blockIdx.x * POOL_CH;
    if (start >= N_NODES) return;
    int end = min(start + POOL_CH, N_NODES);
    int cur = batch[start];
    float acc = 0.f, cnt = 0.f;
    for (int i = start; i < end; i++) {
        int b = batch[i];
        if (b != cur) {
            atomicAdd(&g_pool[cur * HID + t], acc);
            if (t == 0) atomicAdd(&g_cnt[cur], cnt);
            acc = 0.f; cnt = 0.f; cur = b;
        }
        acc += g_h[(size_t)i * HID + t];
        cnt += 1.f;
    }
    atomicAdd(&g_pool[cur * HID + t], acc);
    if (t == 0) atomicAdd(&g_cnt[cur], cnt);
}

// ---------------- final head: mean, embeddings out, logits ----------------
__global__ void final_kernel(const float* __restrict__ Wlin,
                             const float* __restrict__ blin,
                             float* __restrict__ out) {
    int g = blockIdx.x;         // graph
    int t = threadIdx.x;        // 128
    __shared__ float p[HID];
    float c = fmaxf(g_cnt[g], 1.0f);
    float v = g_pool[g * HID + t] / c;
    out[N_GRAPHS * N_CLASSES + g * HID + t] = v;   // embeddings after logits
    p[t] = v;
    __syncthreads();
    if (t < N_CLASSES) {
        float s = blin[t];
        #pragma unroll 8
        for (int j = 0; j < HID; j++) s += p[j] * Wlin[j * N_CLASSES + t];
        out[g * N_CLASSES + t] = s;
    }
}

// ---------------- launch ----------------
extern "C" void kernel_launch(void* const* d_in, const int* in_sizes, int n_in,
                              void* d_out, int out_size)
{
    const float* x     = (const float*)d_in[0];
    const int*   ei    = (const int*)d_in[1];      // int32 (JAX x64 disabled)
    const int*   batch = (const int*)d_in[2];
    const float* W[6] = {(const float*)d_in[3],  (const float*)d_in[5],
                         (const float*)d_in[7],  (const float*)d_in[9],
                         (const float*)d_in[11], (const float*)d_in[13]};
    const float* b[6] = {(const float*)d_in[4],  (const float*)d_in[6],
                         (const float*)d_in[8],  (const float*)d_in[10],
                         (const float*)d_in[12], (const float*)d_in[14]};
    const float* Wlin = (const float*)d_in[15];
    const float* blin = (const float*)d_in[16];
    float* out = (float*)d_out;

    zero_kernel <<<(N_NODES + 255) / 256, 256>>>();
    deg_kernel  <<<(N_EDGES + 255) / 256, 256>>>(ei);
    dinv_kernel <<<(N_NODES + 255) / 256, 256>>>();
    scan_kernel <<<1, 1024>>>();
    place_kernel<<<(N_EDGES + 255) / 256, 256>>>(ei);

    const int gemm_grid   = (N_NODES + TM - 1) / TM;             // 782
    const int gather_grid = (N_NODES * 32 + 255) / 256;          // 6250

    for (int l = 0; l < 5; l++) {
        const float* in  = (l == 0) ? x : nullptr;       // null -> g_agg
        const float* pre = (l == 0) ? nullptr : b[l - 1];
        gemm_kernel<<<gemm_grid, 256>>>(in, W[l], N_NODES, pre, nullptr, 1);
        gather_kernel<<<gather_grid, 256>>>();
    }
    // FC layer: relu(agg5 + b5) @ Wfc, fused relu(+bfc), unscaled output
    gemm_kernel<<<gemm_grid, 256>>>(nullptr, W[5], N_NODES, b[4], b[5], 0);

    pool_kernel <<<(N_NODES + POOL_CH - 1) / POOL_CH, 128>>>(batch);
    final_kernel<<<N_GRAPHS, 128>>>(Wlin, blin, out);
}

// round 6
// speedup vs baseline: 2.9679x; 1.3694x over previous
#include <cuda_runtime.h>
#include <cuda_bf16.h>

#define N_NODES   50000
#define N_EDGES   600000
#define HID       128
#define N_GRAPHS  128
#define N_CLASSES 10

#define SCAN_B    512
#define SCAN_NB   ((N_NODES + SCAN_B - 1) / SCAN_B)    // 98

// ---------------- scratch (no allocation allowed) ----------------
__device__ float g_h  [(size_t)N_NODES * HID];   // 25.6 MB  GEMM output (dinv-scaled for conv layers)
__device__ float g_agg[(size_t)N_NODES * HID];   // 25.6 MB  aggregation buffer
__device__ float g_dinv[N_NODES];
__device__ int   g_deg [N_NODES];                // in-degree (excl. self loop)
__device__ int   g_cur [N_NODES];                // placement cursor
__device__ int   g_rowptr[N_NODES + 1];          // CSR row pointers (by dst)
__device__ int   g_csr_src[N_EDGES];             // CSR source indices
__device__ int   g_bsum[SCAN_NB];                // scan block sums
__device__ float g_pool[N_GRAPHS * HID];
__device__ float g_cnt [N_GRAPHS];

// ---------------- setup kernels ----------------
__global__ void zero_kernel() {
    int i = blockIdx.x * blockDim.x + threadIdx.x;
    if (i < N_NODES)      { g_deg[i] = 0; g_cur[i] = 0; }
    if (i < N_GRAPHS * HID) g_pool[i] = 0.f;
    if (i < N_GRAPHS)       g_cnt[i] = 0.f;
}

__global__ void deg_kernel(const int* __restrict__ ei) {
    int e = blockIdx.x * blockDim.x + threadIdx.x;
    if (e < N_EDGES) atomicAdd(&g_deg[ei[N_EDGES + e]], 1);
}

__global__ void dinv_kernel() {
    int i = blockIdx.x * blockDim.x + threadIdx.x;
    if (i < N_NODES) g_dinv[i] = rsqrtf((float)g_deg[i] + 1.0f);
}

// ---- decoupled scan: phase 1 — per-block inclusive scan + block sum ----
__global__ __launch_bounds__(SCAN_B) void scan1_kernel() {
    __shared__ int s[SCAN_B];
    int i = blockIdx.x * SCAN_B + threadIdx.x;
    int v = (i < N_NODES) ? g_deg[i] : 0;
    s[threadIdx.x] = v;
    __syncthreads();
    #pragma unroll
    for (int off = 1; off < SCAN_B; off <<= 1) {
        int t = (threadIdx.x >= off) ? s[threadIdx.x - off] : 0;
        __syncthreads();
        s[threadIdx.x] += t;
        __syncthreads();
    }
    if (i < N_NODES) g_rowptr[i + 1] = s[threadIdx.x];   // local inclusive
    if (threadIdx.x == SCAN_B - 1) g_bsum[blockIdx.x] = s[SCAN_B - 1];
}

// ---- phase 2 — exclusive scan of SCAN_NB block sums (single small block) ----
__global__ void scan2_kernel() {
    __shared__ int s[128];
    int v = (threadIdx.x < SCAN_NB) ? g_bsum[threadIdx.x] : 0;
    s[threadIdx.x] = v;
    __syncthreads();
    #pragma unroll
    for (int off = 1; off < 128; off <<= 1) {
        int t = (threadIdx.x >= off) ? s[threadIdx.x - off] : 0;
        __syncthreads();
        s[threadIdx.x] += t;
        __syncthreads();
    }
    if (threadIdx.x < SCAN_NB) g_bsum[threadIdx.x] = s[threadIdx.x] - v; // exclusive
}

// ---- phase 3 — add block offsets ----
__global__ void scan3_kernel() {
    int i = blockIdx.x * blockDim.x + threadIdx.x;
    if (i == 0) g_rowptr[0] = 0;
    if (i < N_NODES) g_rowptr[i + 1] += g_bsum[i / SCAN_B];
}

__global__ void place_kernel(const int* __restrict__ ei) {
    int e = blockIdx.x * blockDim.x + threadIdx.x;
    if (e >= N_EDGES) return;
    int r = ei[e];
    int c = ei[N_EDGES + e];
    int pos = g_rowptr[c] + atomicAdd(&g_cur[c], 1);
    g_csr_src[pos] = r;
}

// ---------------- aggregation: pure gather, no atomics ----------------
// g_h holds h_scaled = h*dinv (written by GEMM epilogue).
// agg[i] = dinv[i] * ( h_scaled[i] + sum_{src in N(i)} h_scaled[src] )
__global__ __launch_bounds__(256) void gather_kernel() {
    int gt   = blockIdx.x * blockDim.x + threadIdx.x;
    int node = gt >> 5;
    int lane = gt & 31;
    if (node >= N_NODES) return;

    const float4* h4 = (const float4*)g_h;
    float4 acc = h4[(size_t)node * 32 + lane];     // self-loop term
    float4 acc2 = make_float4(0.f, 0.f, 0.f, 0.f);
    int j  = g_rowptr[node];
    int e1 = g_rowptr[node + 1];

    // 8-deep batches: 8 outstanding loads per lane to cover L2 latency
    for (; j + 8 <= e1; j += 8) {
        int s0 = g_csr_src[j];
        int s1 = g_csr_src[j + 1];
        int s2 = g_csr_src[j + 2];
        int s3 = g_csr_src[j + 3];
        int s4 = g_csr_src[j + 4];
        int s5 = g_csr_src[j + 5];
        int s6 = g_csr_src[j + 6];
        int s7 = g_csr_src[j + 7];
        float4 v0 = h4[(size_t)s0 * 32 + lane];
        float4 v1 = h4[(size_t)s1 * 32 + lane];
        float4 v2 = h4[(size_t)s2 * 32 + lane];
        float4 v3 = h4[(size_t)s3 * 32 + lane];
        float4 v4 = h4[(size_t)s4 * 32 + lane];
        float4 v5 = h4[(size_t)s5 * 32 + lane];
        float4 v6 = h4[(size_t)s6 * 32 + lane];
        float4 v7 = h4[(size_t)s7 * 32 + lane];
        acc.x  += (v0.x + v1.x) + (v2.x + v3.x);
        acc.y  += (v0.y + v1.y) + (v2.y + v3.y);
        acc.z  += (v0.z + v1.z) + (v2.z + v3.z);
        acc.w  += (v0.w + v1.w) + (v2.w + v3.w);
        acc2.x += (v4.x + v5.x) + (v6.x + v7.x);
        acc2.y += (v4.y + v5.y) + (v6.y + v7.y);
        acc2.z += (v4.z + v5.z) + (v6.z + v7.z);
        acc2.w += (v4.w + v5.w) + (v6.w + v7.w);
    }
    if (j + 4 <= e1) {
        int s0 = g_csr_src[j];
        int s1 = g_csr_src[j + 1];
        int s2 = g_csr_src[j + 2];
        int s3 = g_csr_src[j + 3];
        float4 v0 = h4[(size_t)s0 * 32 + lane];
        float4 v1 = h4[(size_t)s1 * 32 + lane];
        float4 v2 = h4[(size_t)s2 * 32 + lane];
        float4 v3 = h4[(size_t)s3 * 32 + lane];
        acc.x += (v0.x + v1.x) + (v2.x + v3.x);
        acc.y += (v0.y + v1.y) + (v2.y + v3.y);
        acc.z += (v0.z + v1.z) + (v2.z + v3.z);
        acc.w += (v0.w + v1.w) + (v2.w + v3.w);
        j += 4;
    }
    for (; j < e1; j++) {
        int s = g_csr_src[j];
        float4 v = h4[(size_t)s * 32 + lane];
        acc.x += v.x; acc.y += v.y; acc.z += v.z; acc.w += v.w;
    }
    acc.x += acc2.x; acc.y += acc2.y; acc.z += acc2.z; acc.w += acc2.w;
    float d = g_dinv[node];
    acc.x *= d; acc.y *= d; acc.z *= d; acc.w *= d;
    ((float4*)g_agg)[(size_t)node * 32 + lane] = acc;
}

// ---------------- GEMM: g_h[n,128] = act(A) @ W[128,128] ----------------
// A == nullptr  -> input is g_agg
// preBias != 0  -> input transform  a = relu(a + preBias[k])
// postBias != 0 -> output transform c = relu(c + postBias[col])
// scaleOut      -> store c * dinv[row]  (conv layers; feeds gather)
#define TM 64

__global__ __launch_bounds__(256) void gemm_kernel(
    const float* __restrict__ A, const float* __restrict__ W, int n,
    const float* __restrict__ preBias, const float* __restrict__ postBias,
    int scaleOut)
{
    __shared__ float ws[64][128];   // 32 KB : k-chunk x col
    __shared__ float xs[64][64];    // 16 KB : row x k-chunk

    const float* Ain = A ? A : g_agg;

    int tid  = threadIdx.x;
    int row0 = blockIdx.x * TM;
    int wid  = tid >> 5;            // 0..7 : rows wid + 8i
    int lane = tid & 31;            // cols lane*2 (+64)

    unsigned long long acc[8][2];
    #pragma unroll
    for (int i = 0; i < 8; i++) { acc[i][0] = 0ull; acc[i][1] = 0ull; }

    #pragma unroll
    for (int kc = 0; kc < 2; kc++) {
        const float4* W4 = (const float4*)(W + kc * 64 * 128);
        #pragma unroll
        for (int i = 0; i < 8; i++) {
            int j = tid + i * 256;
            ((float4*)ws)[j] = W4[j];
        }
        #pragma unroll
        for (int i = 0; i < 4; i++) {
            int j  = tid + i * 256;
            int r  = j >> 4;
            int k4 = j & 15;
            int row = row0 + r;
            float4 v = make_float4(0.f, 0.f, 0.f, 0.f);
            if (row < n) v = ((const float4*)Ain)[row * 32 + kc * 16 + k4];
            if (preBias) {
                float4 b = ((const float4*)preBias)[kc * 16 + k4];
                v.x = fmaxf(v.x + b.x, 0.f);
                v.y = fmaxf(v.y + b.y, 0.f);
                v.z = fmaxf(v.z + b.z, 0.f);
                v.w = fmaxf(v.w + b.w, 0.f);
            }
            *(float4*)&xs[r][k4 * 4] = v;
        }
        __syncthreads();

        #pragma unroll 4
        for (int k = 0; k < 64; k++) {
            unsigned long long b0 = *(const unsigned long long*)&ws[k][lane * 2];
            unsigned long long b1 = *(const unsigned long long*)&ws[k][lane * 2 + 64];
            #pragma unroll
            for (int i = 0; i < 8; i++) {
                float a = xs[wid + 8 * i][k];      // warp-uniform broadcast
                unsigned long long ap;
                asm("mov.b64 %0, {%1, %1};" : "=l"(ap) : "f"(a));
                asm("fma.rn.f32x2 %0, %1, %2, %0;" : "+l"(acc[i][0]) : "l"(ap), "l"(b0));
                asm("fma.rn.f32x2 %0, %1, %2, %0;" : "+l"(acc[i][1]) : "l"(ap), "l"(b1));
            }
        }
        __syncthreads();
    }

    int c0 = lane * 2;
    int c1 = lane * 2 + 64;
    #pragma unroll
    for (int i = 0; i < 8; i++) {
        int row = row0 + wid + 8 * i;
        if (row >= n) continue;
        float lo0, hi0, lo1, hi1;
        asm("mov.b64 {%0, %1}, %2;" : "=f"(lo0), "=f"(hi0) : "l"(acc[i][0]));
        asm("mov.b64 {%0, %1}, %2;" : "=f"(lo1), "=f"(hi1) : "l"(acc[i][1]));
        if (postBias) {
            lo0 = fmaxf(lo0 + postBias[c0],     0.f);
            hi0 = fmaxf(hi0 + postBias[c0 + 1], 0.f);
            lo1 = fmaxf(lo1 + postBias[c1],     0.f);
            hi1 = fmaxf(hi1 + postBias[c1 + 1], 0.f);
        }
        if (scaleOut) {
            float d = g_dinv[row];
            lo0 *= d; hi0 *= d; lo1 *= d; hi1 *= d;
        }
        float2 o0; o0.x = lo0; o0.y = hi0;
        float2 o1; o1.x = lo1; o1.y = hi1;
        *(float2*)&g_h[(size_t)row * HID + c0] = o0;
        *(float2*)&g_h[(size_t)row * HID + c1] = o1;
    }
}

// ---------------- global mean pool (batch is sorted) ----------------
#define POOL_CH 128
__global__ void pool_kernel(const int* __restrict__ batch) {
    int t = threadIdx.x;                        // 128: feature column
    int start = blockIdx.x * POOL_CH;
    if (start >= N_NODES) return;
    int end = min(start + POOL_CH, N_NODES);
    int cur = batch[start];
    float acc = 0.f, cnt = 0.f;
    for (int i = start; i < end; i++) {
        int b = batch[i];
        if (b != cur) {
            atomicAdd(&g_pool[cur * HID + t], acc);
            if (t == 0) atomicAdd(&g_cnt[cur], cnt);
            acc = 0.f; cnt = 0.f; cur = b;
        }
        acc += g_h[(size_t)i * HID + t];
        cnt += 1.f;
    }
    atomicAdd(&g_pool[cur * HID + t], acc);
    if (t == 0) atomicAdd(&g_cnt[cur], cnt);
}

// ---------------- final head: mean, embeddings out, logits ----------------
__global__ void final_kernel(const float* __restrict__ Wlin,
                             const float* __restrict__ blin,
                             float* __restrict__ out) {
    int g = blockIdx.x;         // graph
    int t = threadIdx.x;        // 128
    __shared__ float p[HID];
    float c = fmaxf(g_cnt[g], 1.0f);
    float v = g_pool[g * HID + t] / c;
    out[N_GRAPHS * N_CLASSES + g * HID + t] = v;   // embeddings after logits
    p[t] = v;
    __syncthreads();
    if (t < N_CLASSES) {
        float s = blin[t];
        #pragma unroll 8
        for (int j = 0; j < HID; j++) s += p[j] * Wlin[j * N_CLASSES + t];
        out[g * N_CLASSES + t] = s;
    }
}

// ---------------- launch ----------------
extern "C" void kernel_launch(void* const* d_in, const int* in_sizes, int n_in,
                              void* d_out, int out_size)
{
    const float* x     = (const float*)d_in[0];
    const int*   ei    = (const int*)d_in[1];      // int32 (JAX x64 disabled)
    const int*   batch = (const int*)d_in[2];
    const float* W[6] = {(const float*)d_in[3],  (const float*)d_in[5],
                         (const float*)d_in[7],  (const float*)d_in[9],
                         (const float*)d_in[11], (const float*)d_in[13]};
    const float* b[6] = {(const float*)d_in[4],  (const float*)d_in[6],
                         (const float*)d_in[8],  (const float*)d_in[10],
                         (const float*)d_in[12], (const float*)d_in[14]};
    const float* Wlin = (const float*)d_in[15];
    const float* blin = (const float*)d_in[16];
    float* out = (float*)d_out;

    zero_kernel <<<(N_NODES + 255) / 256, 256>>>();
    deg_kernel  <<<(N_EDGES + 255) / 256, 256>>>(ei);
    dinv_kernel <<<(N_NODES + 255) / 256, 256>>>();
    scan1_kernel<<<SCAN_NB, SCAN_B>>>();
    scan2_kernel<<<1, 128>>>();
    scan3_kernel<<<(N_NODES + 255) / 256, 256>>>();
    place_kernel<<<(N_EDGES + 255) / 256, 256>>>(ei);

    const int gemm_grid   = (N_NODES + TM - 1) / TM;             // 782
    const int gather_grid = (N_NODES * 32 + 255) / 256;          // 6250

    for (int l = 0; l < 5; l++) {
        const float* in  = (l == 0) ? x : nullptr;       // null -> g_agg
        const float* pre = (l == 0) ? nullptr : b[l - 1];
        gemm_kernel<<<gemm_grid, 256>>>(in, W[l], N_NODES, pre, nullptr, 1);
        gather_kernel<<<gather_grid, 256>>>();
    }
    // FC layer: relu(agg5 + b5) @ Wfc, fused relu(+bfc), unscaled output
    gemm_kernel<<<gemm_grid, 256>>>(nullptr, W[5], N_NODES, b[4], b[5], 0);

    pool_kernel <<<(N_NODES + POOL_CH - 1) / POOL_CH, 128>>>(batch);
    final_kernel<<<N_GRAPHS, 128>>>(Wlin, blin, out);
}

// round 8
// speedup vs baseline: 3.7923x; 1.2778x over previous
#include <cuda_runtime.h>
#include <cuda_bf16.h>
#include <cstdint>

#define N_NODES   50000
#define N_EDGES   600000
#define HID       128
#define N_GRAPHS  128
#define N_CLASSES 10

#define SCAN_B    512
#define SCAN_NB   ((N_NODES + SCAN_B - 1) / SCAN_B)    // 98

// ---------------- scratch (no allocation allowed) ----------------
__device__ float g_h  [(size_t)N_NODES * HID];   // GEMM output (dinv-scaled for conv layers)
__device__ float g_agg[(size_t)N_NODES * HID];   // aggregation buffer
__device__ float g_dinv[N_NODES];
__device__ int   g_deg [N_NODES];
__device__ int   g_cur [N_NODES];
__device__ int   g_rowptr[N_NODES + 1];
__device__ int   g_csr_src[N_EDGES];
__device__ int   g_bsum[SCAN_NB];
__device__ float g_pool[N_GRAPHS * HID];
__device__ float g_cnt [N_GRAPHS];
// W in mma.sync B-fragment layout: [layer][term(hi,lo)][kstep][ntile][lane] (b0,b1)
__device__ uint2 g_Bfrag[6][2][8][16][32];

// ---------------- setup kernels ----------------
__global__ void zero_kernel() {
    int i = blockIdx.x * blockDim.x + threadIdx.x;
    if (i < N_NODES)      { g_deg[i] = 0; g_cur[i] = 0; }
    if (i < N_GRAPHS * HID) g_pool[i] = 0.f;
    if (i < N_GRAPHS)       g_cnt[i] = 0.f;
}

__global__ void deg_kernel(const int* __restrict__ ei) {
    int e = blockIdx.x * blockDim.x + threadIdx.x;
    if (e < N_EDGES) atomicAdd(&g_deg[ei[N_EDGES + e]], 1);
}

__global__ void dinv_kernel() {
    int i = blockIdx.x * blockDim.x + threadIdx.x;
    if (i < N_NODES) g_dinv[i] = rsqrtf((float)g_deg[i] + 1.0f);
}

// Build B fragments for mma.m16n8k16 .col (B[k][n] = W[k][n]).
// b0: k = (lane&3)*2 {+0,1}, n = lane>>2 ; b1: k += 8.   (per kstep of 16)
__global__ void wprep_kernel(const float* __restrict__ W, int l) {
    int t = blockIdx.x * blockDim.x + threadIdx.x;   // 0..4095
    if (t >= 8 * 16 * 32) return;
    int s    = t >> 9;          // kstep 0..7
    int j    = (t >> 5) & 15;   // ntile 0..15
    int lane = t & 31;
    int k0 = s * 16 + (lane & 3) * 2;
    int nn = j * 8 + (lane >> 2);
    uint2 hi, lo;
    unsigned hw[2], lw[2];
    #pragma unroll
    for (int q = 0; q < 2; q++) {
        float w0 = W[(k0 + q * 8)     * 128 + nn];
        float w1 = W[(k0 + q * 8 + 1) * 128 + nn];
        __nv_bfloat16 h0 = __float2bfloat16(w0);
        __nv_bfloat16 h1 = __float2bfloat16(w1);
        __nv_bfloat16 l0 = __float2bfloat16(w0 - __bfloat162float(h0));
        __nv_bfloat16 l1 = __float2bfloat16(w1 - __bfloat162float(h1));
        hw[q] = (unsigned)__bfloat16_as_ushort(h0)
              | ((unsigned)__bfloat16_as_ushort(h1) << 16);
        lw[q] = (unsigned)__bfloat16_as_ushort(l0)
              | ((unsigned)__bfloat16_as_ushort(l1) << 16);
    }
    hi.x = hw[0]; hi.y = hw[1];
    lo.x = lw[0]; lo.y = lw[1];
    g_Bfrag[l][0][s][j][lane] = hi;
    g_Bfrag[l][1][s][j][lane] = lo;
}

// ---- decoupled scan ----
__global__ __launch_bounds__(SCAN_B) void scan1_kernel() {
    __shared__ int s[SCAN_B];
    int i = blockIdx.x * SCAN_B + threadIdx.x;
    int v = (i < N_NODES) ? g_deg[i] : 0;
    s[threadIdx.x] = v;
    __syncthreads();
    #pragma unroll
    for (int off = 1; off < SCAN_B; off <<= 1) {
        int t = (threadIdx.x >= off) ? s[threadIdx.x - off] : 0;
        __syncthreads();
        s[threadIdx.x] += t;
        __syncthreads();
    }
    if (i < N_NODES) g_rowptr[i + 1] = s[threadIdx.x];
    if (threadIdx.x == SCAN_B - 1) g_bsum[blockIdx.x] = s[SCAN_B - 1];
}

__global__ void scan2_kernel() {
    __shared__ int s[128];
    int v = (threadIdx.x < SCAN_NB) ? g_bsum[threadIdx.x] : 0;
    s[threadIdx.x] = v;
    __syncthreads();
    #pragma unroll
    for (int off = 1; off < 128; off <<= 1) {
        int t = (threadIdx.x >= off) ? s[threadIdx.x - off] : 0;
        __syncthreads();
        s[threadIdx.x] += t;
        __syncthreads();
    }
    if (threadIdx.x < SCAN_NB) g_bsum[threadIdx.x] = s[threadIdx.x] - v;
}

__global__ void scan3_kernel() {
    int i = blockIdx.x * blockDim.x + threadIdx.x;
    if (i == 0) g_rowptr[0] = 0;
    if (i < N_NODES) g_rowptr[i + 1] += g_bsum[i / SCAN_B];
}

__global__ void place_kernel(const int* __restrict__ ei) {
    int e = blockIdx.x * blockDim.x + threadIdx.x;
    if (e >= N_EDGES) return;
    int r = ei[e];
    int c = ei[N_EDGES + e];
    int pos = g_rowptr[c] + atomicAdd(&g_cur[c], 1);
    g_csr_src[pos] = r;
}

// ---------------- aggregation: pure gather, no atomics ----------------
__global__ __launch_bounds__(256) void gather_kernel() {
    int gt   = blockIdx.x * blockDim.x + threadIdx.x;
    int node = gt >> 5;
    int lane = gt & 31;
    if (node >= N_NODES) return;

    const float4* h4 = (const float4*)g_h;
    float4 acc = h4[(size_t)node * 32 + lane];     // self-loop term
    float4 acc2 = make_float4(0.f, 0.f, 0.f, 0.f);
    int j  = g_rowptr[node];
    int e1 = g_rowptr[node + 1];

    for (; j + 8 <= e1; j += 8) {
        int s0 = g_csr_src[j];
        int s1 = g_csr_src[j + 1];
        int s2 = g_csr_src[j + 2];
        int s3 = g_csr_src[j + 3];
        int s4 = g_csr_src[j + 4];
        int s5 = g_csr_src[j + 5];
        int s6 = g_csr_src[j + 6];
        int s7 = g_csr_src[j + 7];
        float4 v0 = h4[(size_t)s0 * 32 + lane];
        float4 v1 = h4[(size_t)s1 * 32 + lane];
        float4 v2 = h4[(size_t)s2 * 32 + lane];
        float4 v3 = h4[(size_t)s3 * 32 + lane];
        float4 v4 = h4[(size_t)s4 * 32 + lane];
        float4 v5 = h4[(size_t)s5 * 32 + lane];
        float4 v6 = h4[(size_t)s6 * 32 + lane];
        float4 v7 = h4[(size_t)s7 * 32 + lane];
        acc.x  += (v0.x + v1.x) + (v2.x + v3.x);
        acc.y  += (v0.y + v1.y) + (v2.y + v3.y);
        acc.z  += (v0.z + v1.z) + (v2.z + v3.z);
        acc.w  += (v0.w + v1.w) + (v2.w + v3.w);
        acc2.x += (v4.x + v5.x) + (v6.x + v7.x);
        acc2.y += (v4.y + v5.y) + (v6.y + v7.y);
        acc2.z += (v4.z + v5.z) + (v6.z + v7.z);
        acc2.w += (v4.w + v5.w) + (v6.w + v7.w);
    }
    if (j + 4 <= e1) {
        int s0 = g_csr_src[j];
        int s1 = g_csr_src[j + 1];
        int s2 = g_csr_src[j + 2];
        int s3 = g_csr_src[j + 3];
        float4 v0 = h4[(size_t)s0 * 32 + lane];
        float4 v1 = h4[(size_t)s1 * 32 + lane];
        float4 v2 = h4[(size_t)s2 * 32 + lane];
        float4 v3 = h4[(size_t)s3 * 32 + lane];
        acc.x += (v0.x + v1.x) + (v2.x + v3.x);
        acc.y += (v0.y + v1.y) + (v2.y + v3.y);
        acc.z += (v0.z + v1.z) + (v2.z + v3.z);
        acc.w += (v0.w + v1.w) + (v2.w + v3.w);
        j += 4;
    }
    for (; j < e1; j++) {
        int s = g_csr_src[j];
        float4 v = h4[(size_t)s * 32 + lane];
        acc.x += v.x; acc.y += v.y; acc.z += v.z; acc.w += v.w;
    }
    acc.x += acc2.x; acc.y += acc2.y; acc.z += acc2.z; acc.w += acc2.w;
    float d = g_dinv[node];
    acc.x *= d; acc.y *= d; acc.z *= d; acc.w *= d;
    ((float4*)g_agg)[(size_t)node * 32 + lane] = acc;
}

// ---------------- mma.sync GEMM: g_h[tile,128] = act(A) @ W ----------------
// 3-term bf16 split: Ahi*Whi + Alo*Whi + Ahi*Wlo  (fp32 accumulators)
__device__ __forceinline__ void mma_bf16(float* d, const unsigned* a,
                                         const unsigned* b) {
    asm("mma.sync.aligned.m16n8k16.row.col.f32.bf16.bf16.f32 "
        "{%0,%1,%2,%3}, {%4,%5,%6,%7}, {%8,%9}, {%0,%1,%2,%3};"
        : "+f"(d[0]), "+f"(d[1]), "+f"(d[2]), "+f"(d[3])
        : "r"(a[0]), "r"(a[1]), "r"(a[2]), "r"(a[3]), "r"(b[0]), "r"(b[1]));
}

#define A_LD 136                         // padded bf16 row stride
#define SM_B    0                        // 65536 B : B frags (2 terms)
#define SM_AHI  65536                    // 34816 B
#define SM_ALO  (SM_AHI + 128 * A_LD * 2)
#define TC_SMEM (SM_ALO + 128 * A_LD * 2)   // 135168 B

__global__ __launch_bounds__(256) void tc_gemm_kernel(
    const float* __restrict__ A, int layer, int n,
    const float* __restrict__ preBias, const float* __restrict__ postBias,
    int scaleOut)
{
    extern __shared__ char smem[];
    const float* Ain = A ? A : g_agg;

    int tid  = threadIdx.x;
    int lane = tid & 31;
    int wid  = tid >> 5;
    int row0 = blockIdx.x * 128;

    // B fragments: linear 64 KB copy (both terms)
    {
        const float4* src = (const float4*)&g_Bfrag[layer][0][0][0][0];
        float4* dst = (float4*)(smem + SM_B);
        #pragma unroll
        for (int i = 0; i < 16; i++) dst[tid + i * 256] = src[tid + i * 256];
    }
    // A tile: fp32 (+prebias/relu) -> bf16 hi/lo, padded row-major
    __nv_bfloat16* ahiS = (__nv_bfloat16*)(smem + SM_AHI);
    __nv_bfloat16* aloS = (__nv_bfloat16*)(smem + SM_ALO);
    #pragma unroll
    for (int it = 0; it < 32; it++) {
        int j = tid + it * 256;          // pair index 0..8191
        int r = j >> 6;
        int c = (j & 63) * 2;
        int row = row0 + r;
        float2 v = make_float2(0.f, 0.f);
        if (row < n) v = *(const float2*)&Ain[(size_t)row * HID + c];
        if (preBias) {
            v.x = fmaxf(v.x + preBias[c],     0.f);
            v.y = fmaxf(v.y + preBias[c + 1], 0.f);
        }
        __nv_bfloat16 h0 = __float2bfloat16(v.x);
        __nv_bfloat16 h1 = __float2bfloat16(v.y);
        __nv_bfloat16 l0 = __float2bfloat16(v.x - __bfloat162float(h0));
        __nv_bfloat16 l1 = __float2bfloat16(v.y - __bfloat162float(h1));
        unsigned hw = (unsigned)__bfloat16_as_ushort(h0)
                    | ((unsigned)__bfloat16_as_ushort(h1) << 16);
        unsigned lw = (unsigned)__bfloat16_as_ushort(l0)
                    | ((unsigned)__bfloat16_as_ushort(l1) << 16);
        *(unsigned*)&ahiS[r * A_LD + c] = hw;
        *(unsigned*)&aloS[r * A_LD + c] = lw;
    }
    __syncthreads();

    // warp tiling: wm in 0..3 (32-row band), wn in 0..1 (64-col band)
    int wm = wid & 3;
    int wn = wid >> 2;
    int rA = wm * 32 + (lane >> 2);      // fragment base row in tile
    int cGrp = (lane & 3) * 2;           // fragment base col-pair

    float acc[2][8][4];
    #pragma unroll
    for (int i = 0; i < 2; i++)
        #pragma unroll
        for (int j = 0; j < 8; j++)
            #pragma unroll
            for (int q = 0; q < 4; q++) acc[i][j][q] = 0.f;

    const uint2* bfragHi = (const uint2*)(smem + SM_B);
    const uint2* bfragLo = (const uint2*)(smem + SM_B + 32768);

    #pragma unroll
    for (int s = 0; s < 8; s++) {
        int kc = s * 16 + cGrp;          // A fragment k column
        unsigned ahi[2][4], alo[2][4];
        #pragma unroll
        for (int i = 0; i < 2; i++) {
            int r = rA + i * 16;
            ahi[i][0] = *(const unsigned*)&ahiS[(r    ) * A_LD + kc    ];
            ahi[i][1] = *(const unsigned*)&ahiS[(r + 8) * A_LD + kc    ];
            ahi[i][2] = *(const unsigned*)&ahiS[(r    ) * A_LD + kc + 8];
            ahi[i][3] = *(const unsigned*)&ahiS[(r + 8) * A_LD + kc + 8];
            alo[i][0] = *(const unsigned*)&aloS[(r    ) * A_LD + kc    ];
            alo[i][1] = *(const unsigned*)&aloS[(r + 8) * A_LD + kc    ];
            alo[i][2] = *(const unsigned*)&aloS[(r    ) * A_LD + kc + 8];
            alo[i][3] = *(const unsigned*)&aloS[(r + 8) * A_LD + kc + 8];
        }
        uint2 bh[8], bl[8];
        #pragma unroll
        for (int j = 0; j < 8; j++) {
            int nt = wn * 8 + j;
            bh[j] = bfragHi[(s * 16 + nt) * 32 + lane];
            bl[j] = bfragLo[(s * 16 + nt) * 32 + lane];
        }
        #pragma unroll
        for (int i = 0; i < 2; i++)
            #pragma unroll
            for (int j = 0; j < 8; j++) {
                mma_bf16(acc[i][j], ahi[i], (const unsigned*)&bh[j]);
                mma_bf16(acc[i][j], alo[i], (const unsigned*)&bh[j]);
                mma_bf16(acc[i][j], ahi[i], (const unsigned*)&bl[j]);
            }
    }

    // epilogue: d0,d1 -> (rA+i*16, col..col+1); d2,d3 -> (+8 rows)
    #pragma unroll
    for (int i = 0; i < 2; i++) {
        int r0 = row0 + rA + i * 16;
        int r1 = r0 + 8;
        float d0s = 1.f, d1s = 1.f;
        bool ok0 = r0 < n, ok1 = r1 < n;
        if (scaleOut) {
            if (ok0) d0s = g_dinv[r0];
            if (ok1) d1s = g_dinv[r1];
        }
        #pragma unroll
        for (int j = 0; j < 8; j++) {
            int col = wn * 64 + j * 8 + cGrp;
            float v0 = acc[i][j][0], v1 = acc[i][j][1];
            float v2 = acc[i][j][2], v3 = acc[i][j][3];
            if (postBias) {
                float b0 = postBias[col], b1 = postBias[col + 1];
                v0 = fmaxf(v0 + b0, 0.f); v1 = fmaxf(v1 + b1, 0.f);
                v2 = fmaxf(v2 + b0, 0.f); v3 = fmaxf(v3 + b1, 0.f);
            }
            if (ok0) {
                float2 o; o.x = v0 * d0s; o.y = v1 * d0s;
                *(float2*)&g_h[(size_t)r0 * HID + col] = o;
            }
            if (ok1) {
                float2 o; o.x = v2 * d1s; o.y = v3 * d1s;
                *(float2*)&g_h[(size_t)r1 * HID + col] = o;
            }
        }
    }
}

// ---------------- global mean pool (batch is sorted) ----------------
#define POOL_CH 128
__global__ void pool_kernel(const int* __restrict__ batch) {
    int t = threadIdx.x;                        // 128: feature column
    int start = blockIdx.x * POOL_CH;
    if (start >= N_NODES) return;
    int end = min(start + POOL_CH, N_NODES);
    int cur = batch[start];
    float acc = 0.f, cnt = 0.f;
    for (int i = start; i < end; i++) {
        int b = batch[i];
        if (b != cur) {
            atomicAdd(&g_pool[cur * HID + t], acc);
            if (t == 0) atomicAdd(&g_cnt[cur], cnt);
            acc = 0.f; cnt = 0.f; cur = b;
        }
        acc += g_h[(size_t)i * HID + t];
        cnt += 1.f;
    }
    atomicAdd(&g_pool[cur * HID + t], acc);
    if (t == 0) atomicAdd(&g_cnt[cur], cnt);
}

// ---------------- final head: mean, embeddings out, logits ----------------
__global__ void final_kernel(const float* __restrict__ Wlin,
                             const float* __restrict__ blin,
                             float* __restrict__ out) {
    int g = blockIdx.x;
    int t = threadIdx.x;
    __shared__ float p[HID];
    float c = fmaxf(g_cnt[g], 1.0f);
    float v = g_pool[g * HID + t] / c;
    out[N_GRAPHS * N_CLASSES + g * HID + t] = v;
    p[t] = v;
    __syncthreads();
    if (t < N_CLASSES) {
        float s = blin[t];
        #pragma unroll 8
        for (int j = 0; j < HID; j++) s += p[j] * Wlin[j * N_CLASSES + t];
        out[g * N_CLASSES + t] = s;
    }
}

// ---------------- launch ----------------
extern "C" void kernel_launch(void* const* d_in, const int* in_sizes, int n_in,
                              void* d_out, int out_size)
{
    const float* x     = (const float*)d_in[0];
    const int*   ei    = (const int*)d_in[1];      // int32 (JAX x64 disabled)
    const int*   batch = (const int*)d_in[2];
    const float* W[6] = {(const float*)d_in[3],  (const float*)d_in[5],
                         (const float*)d_in[7],  (const float*)d_in[9],
                         (const float*)d_in[11], (const float*)d_in[13]};
    const float* b[6] = {(const float*)d_in[4],  (const float*)d_in[6],
                         (const float*)d_in[8],  (const float*)d_in[10],
                         (const float*)d_in[12], (const float*)d_in[14]};
    const float* Wlin = (const float*)d_in[15];
    const float* blin = (const float*)d_in[16];
    float* out = (float*)d_out;

    cudaFuncSetAttribute(tc_gemm_kernel,
                         cudaFuncAttributeMaxDynamicSharedMemorySize, TC_SMEM);

    zero_kernel <<<(N_NODES + 255) / 256, 256>>>();
    deg_kernel  <<<(N_EDGES + 255) / 256, 256>>>(ei);
    dinv_kernel <<<(N_NODES + 255) / 256, 256>>>();
    scan1_kernel<<<SCAN_NB, SCAN_B>>>();
    scan2_kernel<<<1, 128>>>();
    scan3_kernel<<<(N_NODES + 255) / 256, 256>>>();
    place_kernel<<<(N_EDGES + 255) / 256, 256>>>(ei);
    for (int l = 0; l < 6; l++)
        wprep_kernel<<<16, 256>>>(W[l], l);

    const int gemm_grid   = (N_NODES + 127) / 128;               // 391
    const int gather_grid = (N_NODES * 32 + 255) / 256;          // 6250

    for (int l = 0; l < 5; l++) {
        const float* in  = (l == 0) ? x : nullptr;       // null -> g_agg
        const float* pre = (l == 0) ? nullptr : b[l - 1];
        tc_gemm_kernel<<<gemm_grid, 256, TC_SMEM>>>(in, l, N_NODES, pre, nullptr, 1);
        gather_kernel<<<gather_grid, 256>>>();
    }
    // FC layer: relu(agg5 + b5) @ Wfc, fused relu(+bfc), unscaled output
    tc_gemm_kernel<<<gemm_grid, 256, TC_SMEM>>>(nullptr, 5, N_NODES, b[4], b[5], 0);

    pool_kernel <<<(N_NODES + POOL_CH - 1) / POOL_CH, 128>>>(batch);
    final_kernel<<<N_GRAPHS, 128>>>(Wlin, blin, out);
}